// round 16
// baseline (speedup 1.0000x reference)
#include <cuda_runtime.h>
#include <cuda_bf16.h>
#include <cstdint>
#include <cstddef>

#define NQ    3136
#define CC    256
#define BZV   2
#define NH    8
#define HD    32
#define LL    56
#define DFFN  1024
#define MQ    (BZV*NQ)
#define SCALE 0.17677669529663687f
#define NEGF  (-3.402823466e38f)

// ------------------------- scratch -------------------------------------------
#define SZ_BQC (MQ*CC)
#define SZ_KP  (BZV*LL*CC)
#define SZ_FFN (MQ*DFFN)

#define F_X       ((size_t)0)
#define F_XPR     (F_X    + SZ_BQC)
#define F_XPC     (F_XPR  + SZ_BQC)
#define F_QROW    (F_XPC  + SZ_BQC)
#define F_QCOL    (F_QROW + SZ_BQC)
#define F_ATTN    (F_QCOL + SZ_BQC)
#define F_ATTNOUT (F_ATTN + SZ_BQC)
#define F_X1      (F_ATTNOUT + SZ_BQC)
#define F_Y       (F_X1   + SZ_BQC)
#define F_FFN     (F_Y    + SZ_BQC)
#define F_PR      (F_FFN  + SZ_FFN)
#define F_PC      (F_PR   + SZ_KP)
#define F_KROW    (F_PC   + SZ_KP)
#define F_KCOL    (F_KROW + SZ_KP)
#define F_TOTAL   (F_KCOL + SZ_KP)
__device__ float g_f[F_TOTAL];

// V stored transposed as bf16: Vt[b][n][d][q]
__device__ __nv_bfloat16 g_vt[(size_t)BZV * NH * HD * NQ];

// ------------------------- helpers -------------------------------------------
__device__ __forceinline__ uint32_t pack_bf16(float a, float b) {
    __nv_bfloat162 t = __floats2bfloat162_rn(a, b);
    return *(uint32_t*)&t;
}
__device__ __forceinline__ void mma_tf32(float (&c)[4], const uint32_t (&a)[4],
                                         const uint32_t (&b)[2]) {
    asm volatile("mma.sync.aligned.m16n8k8.row.col.f32.tf32.tf32.f32 "
        "{%0,%1,%2,%3},{%4,%5,%6,%7},{%8,%9},{%0,%1,%2,%3};"
        : "+f"(c[0]), "+f"(c[1]), "+f"(c[2]), "+f"(c[3])
        : "r"(a[0]), "r"(a[1]), "r"(a[2]), "r"(a[3]), "r"(b[0]), "r"(b[1]));
}
__device__ __forceinline__ void mma_bf16(float (&c)[4], const uint32_t (&a)[4],
                                         const uint32_t (&b)[2]) {
    asm volatile("mma.sync.aligned.m16n8k16.row.col.f32.bf16.bf16.f32 "
        "{%0,%1,%2,%3},{%4,%5,%6,%7},{%8,%9},{%0,%1,%2,%3};"
        : "+f"(c[0]), "+f"(c[1]), "+f"(c[2]), "+f"(c[3])
        : "r"(a[0]), "r"(a[1]), "r"(a[2]), "r"(a[3]), "r"(b[0]), "r"(b[1]));
}

// ------------------------- prep ------------------------------------------------
__global__ __launch_bounds__(256) void prep_kernel(
    const float* __restrict__ src, const float* __restrict__ pr,
    const float* __restrict__ pc, float* __restrict__ x,
    float* __restrict__ xpr, float* __restrict__ xpc)
{
    __shared__ float tile[64 * 65];
    int b = blockIdx.z;
    int q0 = blockIdx.x * 64, c0 = blockIdx.y * 64;
    int tid = threadIdx.x;

    int cl_ = tid >> 2, qs = (tid & 3) * 16;
    const float* sp = src + ((size_t)(b * CC + c0 + cl_)) * NQ + q0 + qs;
    #pragma unroll
    for (int j = 0; j < 4; j++) {
        float4 vv = *(const float4*)(sp + j * 4);
        tile[cl_ * 65 + qs + j * 4 + 0] = vv.x;
        tile[cl_ * 65 + qs + j * 4 + 1] = vv.y;
        tile[cl_ * 65 + qs + j * 4 + 2] = vv.z;
        tile[cl_ * 65 + qs + j * 4 + 3] = vv.w;
    }
    __syncthreads();

    int ql = tid >> 2, cs = (tid & 3) * 16;
    int q = q0 + ql;
    int irow = q / LL, jcol = q % LL;
    const float* prp = pr + (size_t)(b * LL + jcol) * CC + c0 + cs;
    const float* pcp = pc + (size_t)(b * LL + irow) * CC + c0 + cs;
    size_t ob = ((size_t)(b * NQ + q)) * CC + c0 + cs;
    #pragma unroll
    for (int j = 0; j < 4; j++) {
        float v0 = tile[(cs + j * 4 + 0) * 65 + ql];
        float v1 = tile[(cs + j * 4 + 1) * 65 + ql];
        float v2 = tile[(cs + j * 4 + 2) * 65 + ql];
        float v3 = tile[(cs + j * 4 + 3) * 65 + ql];
        float4 p4 = *(const float4*)(prp + j * 4);
        float4 c4 = *(const float4*)(pcp + j * 4);
        *(float4*)(x + ob + j * 4) = make_float4(v0, v1, v2, v3);
        *(float4*)(xpr + ob + j * 4) = make_float4(v0 + p4.x, v1 + p4.y, v2 + p4.z, v3 + p4.w);
        *(float4*)(xpc + ob + j * 4) = make_float4(v0 + c4.x, v1 + c4.y, v2 + c4.z, v3 + c4.w);
    }
}

// ------------------------- pooling ---------------------------------------------
__global__ __launch_bounds__(256) void pool_kernel(
    const float* __restrict__ x, const float* __restrict__ pr,
    const float* __restrict__ pc,
    float* __restrict__ pooled_r, float* __restrict__ pooled_c)
{
    int idx = blockIdx.x * 256 + threadIdx.x;
    int c = idx & 255;
    int t = idx >> 8;
    int rc = t % LL;
    int b = t / LL;
    float sr = 0.f, sc = 0.f;
    #pragma unroll 8
    for (int i = 0; i < LL; i++) {
        sr += x[((size_t)(b * NQ) + i * LL + rc) * CC + c];
        sc += x[((size_t)(b * NQ) + rc * LL + i) * CC + c];
    }
    pooled_r[idx] = sr * (1.0f / LL) + pr[idx];
    pooled_c[idx] = sc * (1.0f / LL) + pc[idx];
}

// ------------------------- tf32 GEMM (raw-f32 staging, batched) ------------------
struct GemmJob {
    const float* A;
    const float* B;
    const float* bias;
    float* C;
    __nv_bfloat16* vt;
    float alpha;
    int relu;
    int M;
};
struct GemmArgs { GemmJob j[5]; };

template<int BM, int BN, int WM, int WN>
__global__ __launch_bounds__(256, 2) void gemm_tf32(GemmArgs args, int N, int K)
{
    constexpr int MT = WM / 16, NT = WN / 8;
    constexpr int SA = BM * 20, SB = BN * 20, STG = SA + SB;
    constexpr int AU = BM / 64;
    constexpr int BU = BN / 64;
    __shared__ uint32_t sm[2 * STG];

    const GemmJob jb = args.j[blockIdx.z];
    int M = jb.M;
    int bm = blockIdx.y * BM, bn = blockIdx.x * BN;
    if (bm >= M) return;
    int tid = threadIdx.x, warp = tid >> 5, lane = tid & 31;
    constexpr int WARPS_M = BM / WM;
    int wm = warp % WARPS_M, wn = warp / WARPS_M;
    int g = lane >> 2, tq = lane & 3;
    int R0 = wm * WM, N0 = wn * WN;

    float acc[MT][NT][4];
    #pragma unroll
    for (int mt = 0; mt < MT; mt++)
        #pragma unroll
        for (int nt = 0; nt < NT; nt++)
            #pragma unroll
            for (int i = 0; i < 4; i++) acc[mt][nt][i] = 0.f;

    int KT = K >> 4;
    uint4 rA[AU], rB[BU];
    int arow[AU], akq[AU], brow[BU], bkq[BU];
    #pragma unroll
    for (int i = 0; i < AU; i++) {
        int idx = tid + i * 256;
        arow[i] = idx >> 2; akq[i] = (idx & 3) * 4;
    }
    #pragma unroll
    for (int i = 0; i < BU; i++) {
        int idx = tid + i * 256;
        brow[i] = idx >> 2; bkq[i] = (idx & 3) * 4;
    }

    #pragma unroll
    for (int i = 0; i < AU; i++) {
        rA[i] = make_uint4(0u, 0u, 0u, 0u);
        if (bm + arow[i] < M)
            rA[i] = *(const uint4*)(jb.A + (size_t)(bm + arow[i]) * K + akq[i]);
    }
    #pragma unroll
    for (int i = 0; i < BU; i++)
        rB[i] = *(const uint4*)(jb.B + (size_t)(bn + brow[i]) * K + bkq[i]);
    #pragma unroll
    for (int i = 0; i < AU; i++)
        *(uint4*)(sm + arow[i] * 20 + akq[i]) = rA[i];
    #pragma unroll
    for (int i = 0; i < BU; i++)
        *(uint4*)(sm + SA + brow[i] * 20 + bkq[i]) = rB[i];
    __syncthreads();

    for (int kt = 0; kt < KT; kt++) {
        int s = kt & 1;
        if (kt + 1 < KT) {
            int k0 = (kt + 1) * 16;
            #pragma unroll
            for (int i = 0; i < AU; i++)
                if (bm + arow[i] < M)
                    rA[i] = *(const uint4*)(jb.A + (size_t)(bm + arow[i]) * K + k0 + akq[i]);
            #pragma unroll
            for (int i = 0; i < BU; i++)
                rB[i] = *(const uint4*)(jb.B + (size_t)(bn + brow[i]) * K + k0 + bkq[i]);
        }
        const uint32_t* sA = sm + s * STG;
        const uint32_t* sB = sA + SA;
        #pragma unroll
        for (int ks = 0; ks < 2; ks++) {
            int ko = ks * 8;
            uint32_t aF[MT][4], bF[NT][2];
            #pragma unroll
            for (int mt = 0; mt < MT; mt++) {
                int r = R0 + mt * 16 + g;
                aF[mt][0] = sA[r * 20 + ko + tq];
                aF[mt][1] = sA[(r + 8) * 20 + ko + tq];
                aF[mt][2] = sA[r * 20 + ko + tq + 4];
                aF[mt][3] = sA[(r + 8) * 20 + ko + tq + 4];
            }
            #pragma unroll
            for (int nt = 0; nt < NT; nt++) {
                int rn = N0 + nt * 8 + g;
                bF[nt][0] = sB[rn * 20 + ko + tq];
                bF[nt][1] = sB[rn * 20 + ko + tq + 4];
            }
            #pragma unroll
            for (int mt = 0; mt < MT; mt++)
                #pragma unroll
                for (int nt = 0; nt < NT; nt++)
                    mma_tf32(acc[mt][nt], aF[mt], bF[nt]);
        }
        if (kt + 1 < KT) {
            uint32_t* dA = sm + (s ^ 1) * STG;
            uint32_t* dB = dA + SA;
            #pragma unroll
            for (int i = 0; i < AU; i++)
                *(uint4*)(dA + arow[i] * 20 + akq[i]) = rA[i];
            #pragma unroll
            for (int i = 0; i < BU; i++)
                *(uint4*)(dB + brow[i] * 20 + bkq[i]) = rB[i];
            __syncthreads();
        }
    }

    #pragma unroll
    for (int mt = 0; mt < MT; mt++)
        #pragma unroll
        for (int nt = 0; nt < NT; nt++) {
            int r = bm + R0 + mt * 16 + g;
            int cn = bn + N0 + nt * 8 + tq * 2;
            float b0 = jb.bias[cn], b1 = jb.bias[cn + 1];
            float o0 = (acc[mt][nt][0] + b0) * jb.alpha;
            float o1 = (acc[mt][nt][1] + b1) * jb.alpha;
            float o2 = (acc[mt][nt][2] + b0) * jb.alpha;
            float o3 = (acc[mt][nt][3] + b1) * jb.alpha;
            if (jb.relu) {
                o0 = fmaxf(o0, 0.f); o1 = fmaxf(o1, 0.f);
                o2 = fmaxf(o2, 0.f); o3 = fmaxf(o3, 0.f);
            }
            if (jb.vt) {
                int n0 = cn >> 5, d0 = cn & 31;
                if (r < M) {
                    int bb = r / NQ, q = r - bb * NQ;
                    size_t base = ((size_t)(bb * NH + n0) * HD) * NQ + q;
                    jb.vt[base + (size_t)d0 * NQ]       = __float2bfloat16(o0);
                    jb.vt[base + (size_t)(d0 + 1) * NQ] = __float2bfloat16(o1);
                }
                if (r + 8 < M) {
                    int bb = (r + 8) / NQ, q = (r + 8) - bb * NQ;
                    size_t base = ((size_t)(bb * NH + n0) * HD) * NQ + q;
                    jb.vt[base + (size_t)d0 * NQ]       = __float2bfloat16(o2);
                    jb.vt[base + (size_t)(d0 + 1) * NQ] = __float2bfloat16(o3);
                }
            } else {
                if (r < M)
                    *(float2*)(jb.C + (size_t)r * N + cn) = make_float2(o0, o1);
                if (r + 8 < M)
                    *(float2*)(jb.C + (size_t)(r + 8) * N + cn) = make_float2(o2, o3);
            }
        }
}

// ------------------------- fused attention (gmem-direct V combine) --------------
// smem (u32): ARs[2304] bf16 p36 | ACs[3648] f32 p57 | QKr[4608] | QKc[4608]
// Combine loads V B-fragments straight from gmem (L2-resident), no staging,
// no per-h barriers.
#define AT_ARS  0
#define AT_ACS  2304
#define AT_QKR  (2304+3648)
#define AT_QKC  (AT_QKR + 4608)
#define AT_TOTAL_U32 (AT_QKC + 4608)

__global__ __launch_bounds__(256) void attn_fused(
    const float* __restrict__ qr, const float* __restrict__ qc,
    const float* __restrict__ kr, const float* __restrict__ kc,
    const unsigned char* __restrict__ mask,
    const __nv_bfloat16* __restrict__ vt, float* __restrict__ attn)
{
    extern __shared__ uint32_t dyn[];
    uint32_t* ARs = dyn + AT_ARS;
    float*    ACs = (float*)(dyn + AT_ACS);
    __shared__ unsigned char Ms[2][64];

    int b = blockIdx.z, n = blockIdx.y, q0 = blockIdx.x * 64;
    int tid = threadIdx.x, warp = tid >> 5, lane = tid & 31;
    int g = lane >> 2, tq = lane & 3;

    // zero ARs K-pad
    for (int i = tid; i < 64 * 4; i += 256) {
        int q = i >> 2;
        ARs[q * 36 + 28 + (i & 3)] = 0;
    }

    // ---- score phases IN PARALLEL: warps 0-3 row, warps 4-7 col ----
    {
        int which = warp >> 2;
        int wl = warp & 3;
        int ht = tid & 127;
        const float* q  = which ? qc : qr;
        const float* kk = which ? kc : kr;
        int mstride     = which ? LL : 1;
        uint32_t* Qs = dyn + (which ? AT_QKC : AT_QKR);
        uint32_t* Ks = Qs + 2304;

        {
            int rq = ht >> 1, hf = (ht & 1) * 16;
            const uint32_t* qp = (const uint32_t*)(q + ((size_t)(b * NQ + q0 + rq)) * CC + n * HD + hf);
            #pragma unroll
            for (int j = 0; j < 4; j++)
                *(uint4*)(Qs + rq * 36 + hf + j * 4) = *(const uint4*)(qp + j * 4);
        }
        for (int i = ht; i < LL * HD; i += 128) {
            int l = i >> 5, d = i & 31;
            Ks[d * 72 + l] = __float_as_uint(kk[((size_t)(b * LL + l)) * CC + n * HD + d]);
        }
        if (ht < LL) Ms[which][ht] = mask[b * NQ + ht * mstride];
        __syncthreads();

        int rb = wl * 16;
        uint32_t a[4][4];
        #pragma unroll
        for (int ks = 0; ks < 4; ks++) {
            a[ks][0] = Qs[(rb + g) * 36 + ks * 8 + tq];
            a[ks][1] = Qs[(rb + g + 8) * 36 + ks * 8 + tq];
            a[ks][2] = Qs[(rb + g) * 36 + ks * 8 + tq + 4];
            a[ks][3] = Qs[(rb + g + 8) * 36 + ks * 8 + tq + 4];
        }
        float c[7][4];
        #pragma unroll
        for (int nt = 0; nt < 7; nt++)
            #pragma unroll
            for (int i = 0; i < 4; i++) c[nt][i] = 0.f;
        #pragma unroll
        for (int nt = 0; nt < 7; nt++)
            #pragma unroll
            for (int ks = 0; ks < 4; ks++) {
                uint32_t bf[2] = { Ks[(ks * 8 + tq) * 72 + nt * 8 + g],
                                   Ks[(ks * 8 + tq + 4) * 72 + nt * 8 + g] };
                mma_tf32(c[nt], a[ks], bf);
            }

        float m0 = -3.0e38f, m1 = -3.0e38f;
        #pragma unroll
        for (int nt = 0; nt < 7; nt++) {
            int col = nt * 8 + tq * 2;
            if (Ms[which][col])     { c[nt][0] = NEGF; c[nt][2] = NEGF; }
            if (Ms[which][col + 1]) { c[nt][1] = NEGF; c[nt][3] = NEGF; }
            m0 = fmaxf(m0, fmaxf(c[nt][0], c[nt][1]));
            m1 = fmaxf(m1, fmaxf(c[nt][2], c[nt][3]));
        }
        #pragma unroll
        for (int o = 1; o <= 2; o <<= 1) {
            m0 = fmaxf(m0, __shfl_xor_sync(0xffffffffu, m0, o));
            m1 = fmaxf(m1, __shfl_xor_sync(0xffffffffu, m1, o));
        }
        float s0 = 0.f, s1 = 0.f;
        #pragma unroll
        for (int nt = 0; nt < 7; nt++) {
            c[nt][0] = __expf(c[nt][0] - m0);
            c[nt][1] = __expf(c[nt][1] - m0);
            c[nt][2] = __expf(c[nt][2] - m1);
            c[nt][3] = __expf(c[nt][3] - m1);
            s0 += c[nt][0] + c[nt][1];
            s1 += c[nt][2] + c[nt][3];
        }
        #pragma unroll
        for (int o = 1; o <= 2; o <<= 1) {
            s0 += __shfl_xor_sync(0xffffffffu, s0, o);
            s1 += __shfl_xor_sync(0xffffffffu, s1, o);
        }
        float i0 = 1.0f / s0, i1 = 1.0f / s1;
        if (which == 0) {
            #pragma unroll
            for (int nt = 0; nt < 7; nt++) {
                ARs[(rb + g) * 36 + nt * 4 + tq]     = pack_bf16(c[nt][0] * i0, c[nt][1] * i0);
                ARs[(rb + g + 8) * 36 + nt * 4 + tq] = pack_bf16(c[nt][2] * i1, c[nt][3] * i1);
            }
        } else {
            #pragma unroll
            for (int nt = 0; nt < 7; nt++) {
                int col = nt * 8 + tq * 2;
                ACs[(rb + g) * 57 + col]         = c[nt][0] * i0;
                ACs[(rb + g) * 57 + col + 1]     = c[nt][1] * i0;
                ACs[(rb + g + 8) * 57 + col]     = c[nt][2] * i1;
                ACs[(rb + g + 8) * 57 + col + 1] = c[nt][3] * i1;
            }
        }
    }
    __syncthreads();

    // ---- combine: bf16 m16n8k16, 8 warps 2(q) x 4(d), V direct from gmem ----
    int wq = warp & 1, wd = warp >> 1;
    int QB = wq * 32, DB = wd * 8;

    uint32_t af[4][2][4];
    #pragma unroll
    for (int ks = 0; ks < 4; ks++)
        #pragma unroll
        for (int mt = 0; mt < 2; mt++) {
            int r = QB + mt * 16 + g;
            af[ks][mt][0] = ARs[r * 36 + ks * 8 + tq];
            af[ks][mt][1] = ARs[(r + 8) * 36 + ks * 8 + tq];
            af[ks][mt][2] = ARs[r * 36 + ks * 8 + tq + 4];
            af[ks][mt][3] = ARs[(r + 8) * 36 + ks * 8 + tq + 4];
        }

    // per-lane V fragment base pointer: row (DB+g) of Vt[d][q] (u32 view, 1568/row)
    const uint32_t* vrow = (const uint32_t*)(vt + ((size_t)(b * NH + n) * HD) * NQ)
                           + (size_t)(DB + g) * (NQ / 2) + tq;

    float oacc[2][4];
    #pragma unroll
    for (int mt = 0; mt < 2; mt++)
        #pragma unroll
        for (int i = 0; i < 4; i++) oacc[mt][i] = 0.f;

    // double-buffered B fragments across h
    uint32_t bfb[2][4][2];
    #pragma unroll
    for (int ks = 0; ks < 4; ks++) {
        bfb[0][ks][0] = vrow[ks * 8];          // h = 0: base offset 0*28
        bfb[0][ks][1] = vrow[ks * 8 + 4];
    }

    for (int h = 0; h < LL; h++) {
        int cur = h & 1;
        if (h + 1 < LL) {
            const uint32_t* vn = vrow + (h + 1) * 28;
            #pragma unroll
            for (int ks = 0; ks < 4; ks++) {
                bfb[cur ^ 1][ks][0] = vn[ks * 8];
                bfb[cur ^ 1][ks][1] = vn[ks * 8 + 4];
            }
        }
        float p[2][4];
        #pragma unroll
        for (int mt = 0; mt < 2; mt++)
            #pragma unroll
            for (int i = 0; i < 4; i++) p[mt][i] = 0.f;
        #pragma unroll
        for (int ks = 0; ks < 4; ks++)
            #pragma unroll
            for (int mt = 0; mt < 2; mt++)
                mma_bf16(p[mt], af[ks][mt], bfb[cur][ks]);

        #pragma unroll
        for (int mt = 0; mt < 2; mt++) {
            float ac0 = ACs[(QB + mt * 16 + g) * 57 + h];
            float ac1 = ACs[(QB + mt * 16 + g + 8) * 57 + h];
            oacc[mt][0] += ac0 * p[mt][0];
            oacc[mt][1] += ac0 * p[mt][1];
            oacc[mt][2] += ac1 * p[mt][2];
            oacc[mt][3] += ac1 * p[mt][3];
        }
    }

    #pragma unroll
    for (int mt = 0; mt < 2; mt++) {
        int r = q0 + QB + mt * 16 + g;
        int col = n * HD + DB + tq * 2;
        *(float2*)(attn + ((size_t)(b * NQ) + r) * CC + col)
            = make_float2(oacc[mt][0], oacc[mt][1]);
        *(float2*)(attn + ((size_t)(b * NQ) + r + 8) * CC + col)
            = make_float2(oacc[mt][2], oacc[mt][3]);
    }
}

// ------------------------- residual + layernorm --------------------------------
__global__ __launch_bounds__(256) void add_ln(
    const float* __restrict__ A, const float* __restrict__ B,
    const float* __restrict__ gg, const float* __restrict__ be,
    float* __restrict__ out, int transpose_out)
{
    __shared__ float tile[256 * 33];
    int row0 = blockIdx.x * 32;
    int b = row0 / NQ;
    int qg0 = row0 % NQ;
    int tid = threadIdx.x, warp = tid >> 5, lane = tid & 31;

    float4 g0 = *(const float4*)(gg + lane * 4);
    float4 g1 = *(const float4*)(gg + 128 + lane * 4);
    float4 e0 = *(const float4*)(be + lane * 4);
    float4 e1 = *(const float4*)(be + 128 + lane * 4);

    #pragma unroll
    for (int rr = 0; rr < 4; rr++) {
        int rloc = warp * 4 + rr;
        size_t base = (size_t)(row0 + rloc) * CC;
        float4 a0 = *(const float4*)(A + base + lane * 4);
        float4 b0 = *(const float4*)(B + base + lane * 4);
        float4 a1 = *(const float4*)(A + base + 128 + lane * 4);
        float4 b1 = *(const float4*)(B + base + 128 + lane * 4);
        float v0x = a0.x + b0.x, v0y = a0.y + b0.y, v0z = a0.z + b0.z, v0w = a0.w + b0.w;
        float v1x = a1.x + b1.x, v1y = a1.y + b1.y, v1z = a1.z + b1.z, v1w = a1.w + b1.w;
        float s  = v0x + v0y + v0z + v0w + v1x + v1y + v1z + v1w;
        float s2 = v0x*v0x + v0y*v0y + v0z*v0z + v0w*v0w
                 + v1x*v1x + v1y*v1y + v1z*v1z + v1w*v1w;
        #pragma unroll
        for (int o = 16; o; o >>= 1) {
            s  += __shfl_xor_sync(0xffffffffu, s,  o);
            s2 += __shfl_xor_sync(0xffffffffu, s2, o);
        }
        float mean = s * (1.0f / CC);
        float var = s2 * (1.0f / CC) - mean * mean;
        float rstd = rsqrtf(var + 1e-5f);
        float r0x = (v0x - mean) * rstd * g0.x + e0.x;
        float r0y = (v0y - mean) * rstd * g0.y + e0.y;
        float r0z = (v0z - mean) * rstd * g0.z + e0.z;
        float r0w = (v0w - mean) * rstd * g0.w + e0.w;
        float r1x = (v1x - mean) * rstd * g1.x + e1.x;
        float r1y = (v1y - mean) * rstd * g1.y + e1.y;
        float r1z = (v1z - mean) * rstd * g1.z + e1.z;
        float r1w = (v1w - mean) * rstd * g1.w + e1.w;
        if (!transpose_out) {
            *(float4*)(out + base + lane * 4) = make_float4(r0x, r0y, r0z, r0w);
            *(float4*)(out + base + 128 + lane * 4) = make_float4(r1x, r1y, r1z, r1w);
        } else {
            int c = lane * 4;
            tile[(c + 0) * 33 + rloc] = r0x;
            tile[(c + 1) * 33 + rloc] = r0y;
            tile[(c + 2) * 33 + rloc] = r0z;
            tile[(c + 3) * 33 + rloc] = r0w;
            tile[(c + 128) * 33 + rloc] = r1x;
            tile[(c + 129) * 33 + rloc] = r1y;
            tile[(c + 130) * 33 + rloc] = r1z;
            tile[(c + 131) * 33 + rloc] = r1w;
        }
    }
    if (transpose_out) {
        __syncthreads();
        int qv = tid & 31;
        int cb = tid >> 5;
        #pragma unroll 8
        for (int k = 0; k < 32; k++) {
            int c = cb + k * 8;
            out[((size_t)(b * CC + c)) * NQ + qg0 + qv] = tile[c * 33 + qv];
        }
    }
}

// ------------------------- launch ----------------------------------------------
extern "C" void kernel_launch(void* const* d_in, const int* in_sizes, int n_in,
                              void* d_out, int out_size)
{
    const float* src   = (const float*)d_in[0];
    const unsigned char* pm = (const unsigned char*)d_in[1];
    const float* pr    = (const float*)d_in[2];
    const float* pc    = (const float*)d_in[3];
    const float* w_q_row = (const float*)d_in[4];
    const float* b_q_row = (const float*)d_in[5];
    const float* w_q_col = (const float*)d_in[6];
    const float* b_q_col = (const float*)d_in[7];
    const float* w_k_row = (const float*)d_in[8];
    const float* b_k_row = (const float*)d_in[9];
    const float* w_k_col = (const float*)d_in[10];
    const float* b_k_col = (const float*)d_in[11];
    const float* w_v   = (const float*)d_in[12];
    const float* b_v   = (const float*)d_in[13];
    const float* w_out = (const float*)d_in[14];
    const float* b_out = (const float*)d_in[15];
    const float* n1g   = (const float*)d_in[16];
    const float* n1b   = (const float*)d_in[17];
    const float* l1w   = (const float*)d_in[18];
    const float* l1b   = (const float*)d_in[19];
    const float* l2w   = (const float*)d_in[20];
    const float* l2b   = (const float*)d_in[21];
    const float* n2g   = (const float*)d_in[22];
    const float* n2b   = (const float*)d_in[23];
    float* out = (float*)d_out;

    float* F = nullptr;
    __nv_bfloat16* VT = nullptr;
    cudaGetSymbolAddress((void**)&F, g_f);
    cudaGetSymbolAddress((void**)&VT, g_vt);
    cudaFuncSetAttribute(attn_fused, cudaFuncAttributeMaxDynamicSharedMemorySize,
                         AT_TOTAL_U32 * 4);

    prep_kernel<<<dim3(NQ / 64, CC / 64, BZV), 256>>>(
        src, pr, pc, F + F_X, F + F_XPR, F + F_XPC);

    pool_kernel<<<BZV * LL * CC / 256, 256>>>(
        F + F_X, pr, pc, F + F_PR, F + F_PC);

    {
        GemmArgs a;
        a.j[0] = {F+F_XPR, w_q_row, b_q_row, F+F_QROW, nullptr, SCALE, 0, MQ};
        a.j[1] = {F+F_XPC, w_q_col, b_q_col, F+F_QCOL, nullptr, SCALE, 0, MQ};
        a.j[2] = {F+F_X,   w_v,     b_v,     nullptr,  VT,      1.0f, 0, MQ};
        a.j[3] = {F+F_PR,  w_k_row, b_k_row, F+F_KROW, nullptr, 1.0f, 0, BZV*LL};
        a.j[4] = {F+F_PC,  w_k_col, b_k_col, F+F_KCOL, nullptr, 1.0f, 0, BZV*LL};
        gemm_tf32<128,128,64,32><<<dim3(CC/128, MQ/128, 5), 256>>>(a, CC, CC);
    }

    attn_fused<<<dim3(NQ/64, NH, BZV), 256, AT_TOTAL_U32 * 4>>>(
        F+F_QROW, F+F_QCOL, F+F_KROW, F+F_KCOL, pm, VT, F+F_ATTN);

    {
        GemmArgs a;
        a.j[0] = {F+F_ATTN, w_out, b_out, F+F_ATTNOUT, nullptr, 1.0f, 0, MQ};
        a.j[1] = a.j[0]; a.j[2] = a.j[0]; a.j[3] = a.j[0]; a.j[4] = a.j[0];
        gemm_tf32<128,128,64,32><<<dim3(CC/128, MQ/128, 1), 256>>>(a, CC, CC);
    }
    add_ln<<<MQ/32, 256>>>(F+F_X, F+F_ATTNOUT, n1g, n1b, F+F_X1, 0);

    {
        GemmArgs a;
        a.j[0] = {F+F_X1, l1w, l1b, F+F_FFN, nullptr, 1.0f, 1, MQ};
        a.j[1] = a.j[0]; a.j[2] = a.j[0]; a.j[3] = a.j[0]; a.j[4] = a.j[0];
        gemm_tf32<128,128,64,32><<<dim3(DFFN/128, MQ/128, 1), 256>>>(a, DFFN, CC);
    }
    {
        GemmArgs a;
        a.j[0] = {F+F_FFN, l2w, l2b, F+F_Y, nullptr, 1.0f, 0, MQ};
        a.j[1] = a.j[0]; a.j[2] = a.j[0]; a.j[3] = a.j[0]; a.j[4] = a.j[0];
        gemm_tf32<128,128,64,32><<<dim3(CC/128, MQ/128, 1), 256>>>(a, CC, DFFN);
    }
    add_ln<<<MQ/32, 256>>>(F+F_X1, F+F_Y, n2g, n2b, out, 1);
}

// round 17
// speedup vs baseline: 1.2022x; 1.2022x over previous
#include <cuda_runtime.h>
#include <cuda_bf16.h>
#include <cstdint>
#include <cstddef>

#define NQ    3136
#define CC    256
#define BZV   2
#define NH    8
#define HD    32
#define LL    56
#define DFFN  1024
#define MQ    (BZV*NQ)
#define SCALE 0.17677669529663687f
#define NEGF  (-3.402823466e38f)

// ------------------------- scratch -------------------------------------------
#define SZ_BQC (MQ*CC)
#define SZ_KP  (BZV*LL*CC)
#define SZ_FFN (MQ*DFFN)

#define F_X       ((size_t)0)
#define F_XPR     (F_X    + SZ_BQC)
#define F_XPC     (F_XPR  + SZ_BQC)
#define F_QROW    (F_XPC  + SZ_BQC)
#define F_QCOL    (F_QROW + SZ_BQC)
#define F_ATTN    (F_QCOL + SZ_BQC)
#define F_ATTNOUT (F_ATTN + SZ_BQC)
#define F_X1      (F_ATTNOUT + SZ_BQC)
#define F_Y       (F_X1   + SZ_BQC)
#define F_FFN     (F_Y    + SZ_BQC)
#define F_PR      (F_FFN  + SZ_FFN)
#define F_PC      (F_PR   + SZ_KP)
#define F_KROW    (F_PC   + SZ_KP)
#define F_KCOL    (F_KROW + SZ_KP)
#define F_TOTAL   (F_KCOL + SZ_KP)
__device__ float g_f[F_TOTAL];

// V stored transposed as bf16: Vt[b][n][d][q]
__device__ __nv_bfloat16 g_vt[(size_t)BZV * NH * HD * NQ];

// ------------------------- helpers -------------------------------------------
__device__ __forceinline__ uint32_t pack_bf16(float a, float b) {
    __nv_bfloat162 t = __floats2bfloat162_rn(a, b);
    return *(uint32_t*)&t;
}
__device__ __forceinline__ void mma_tf32(float (&c)[4], const uint32_t (&a)[4],
                                         const uint32_t (&b)[2]) {
    asm volatile("mma.sync.aligned.m16n8k8.row.col.f32.tf32.tf32.f32 "
        "{%0,%1,%2,%3},{%4,%5,%6,%7},{%8,%9},{%0,%1,%2,%3};"
        : "+f"(c[0]), "+f"(c[1]), "+f"(c[2]), "+f"(c[3])
        : "r"(a[0]), "r"(a[1]), "r"(a[2]), "r"(a[3]), "r"(b[0]), "r"(b[1]));
}
__device__ __forceinline__ void mma_bf16(float (&c)[4], const uint32_t (&a)[4],
                                         const uint32_t (&b)[2]) {
    asm volatile("mma.sync.aligned.m16n8k16.row.col.f32.bf16.bf16.f32 "
        "{%0,%1,%2,%3},{%4,%5,%6,%7},{%8,%9},{%0,%1,%2,%3};"
        : "+f"(c[0]), "+f"(c[1]), "+f"(c[2]), "+f"(c[3])
        : "r"(a[0]), "r"(a[1]), "r"(a[2]), "r"(a[3]), "r"(b[0]), "r"(b[1]));
}
__device__ __forceinline__ void cpa16(uint32_t dst, const void* src, int sz) {
    asm volatile("cp.async.cg.shared.global [%0], [%1], 16, %2;"
        :: "r"(dst), "l"(src), "r"(sz) : "memory");
}
#define CP_COMMIT() asm volatile("cp.async.commit_group;" ::: "memory")
#define CP_WAIT0()  asm volatile("cp.async.wait_group 0;" ::: "memory")

// ------------------------- prep ------------------------------------------------
__global__ __launch_bounds__(256) void prep_kernel(
    const float* __restrict__ src, const float* __restrict__ pr,
    const float* __restrict__ pc, float* __restrict__ x,
    float* __restrict__ xpr, float* __restrict__ xpc)
{
    __shared__ float tile[64 * 65];
    int b = blockIdx.z;
    int q0 = blockIdx.x * 64, c0 = blockIdx.y * 64;
    int tid = threadIdx.x;

    int cl_ = tid >> 2, qs = (tid & 3) * 16;
    const float* sp = src + ((size_t)(b * CC + c0 + cl_)) * NQ + q0 + qs;
    #pragma unroll
    for (int j = 0; j < 4; j++) {
        float4 vv = *(const float4*)(sp + j * 4);
        tile[cl_ * 65 + qs + j * 4 + 0] = vv.x;
        tile[cl_ * 65 + qs + j * 4 + 1] = vv.y;
        tile[cl_ * 65 + qs + j * 4 + 2] = vv.z;
        tile[cl_ * 65 + qs + j * 4 + 3] = vv.w;
    }
    __syncthreads();

    int ql = tid >> 2, cs = (tid & 3) * 16;
    int q = q0 + ql;
    int irow = q / LL, jcol = q % LL;
    const float* prp = pr + (size_t)(b * LL + jcol) * CC + c0 + cs;
    const float* pcp = pc + (size_t)(b * LL + irow) * CC + c0 + cs;
    size_t ob = ((size_t)(b * NQ + q)) * CC + c0 + cs;
    #pragma unroll
    for (int j = 0; j < 4; j++) {
        float v0 = tile[(cs + j * 4 + 0) * 65 + ql];
        float v1 = tile[(cs + j * 4 + 1) * 65 + ql];
        float v2 = tile[(cs + j * 4 + 2) * 65 + ql];
        float v3 = tile[(cs + j * 4 + 3) * 65 + ql];
        float4 p4 = *(const float4*)(prp + j * 4);
        float4 c4 = *(const float4*)(pcp + j * 4);
        *(float4*)(x + ob + j * 4) = make_float4(v0, v1, v2, v3);
        *(float4*)(xpr + ob + j * 4) = make_float4(v0 + p4.x, v1 + p4.y, v2 + p4.z, v3 + p4.w);
        *(float4*)(xpc + ob + j * 4) = make_float4(v0 + c4.x, v1 + c4.y, v2 + c4.z, v3 + c4.w);
    }
}

// ------------------------- pooling ---------------------------------------------
__global__ __launch_bounds__(256) void pool_kernel(
    const float* __restrict__ x, const float* __restrict__ pr,
    const float* __restrict__ pc,
    float* __restrict__ pooled_r, float* __restrict__ pooled_c)
{
    int idx = blockIdx.x * 256 + threadIdx.x;
    int c = idx & 255;
    int t = idx >> 8;
    int rc = t % LL;
    int b = t / LL;
    float sr = 0.f, sc = 0.f;
    #pragma unroll 8
    for (int i = 0; i < LL; i++) {
        sr += x[((size_t)(b * NQ) + i * LL + rc) * CC + c];
        sc += x[((size_t)(b * NQ) + rc * LL + i) * CC + c];
    }
    pooled_r[idx] = sr * (1.0f / LL) + pr[idx];
    pooled_c[idx] = sc * (1.0f / LL) + pc[idx];
}

// ------------------------- tf32 GEMM (cp.async staging, batched) ----------------
struct GemmJob {
    const float* A;
    const float* B;
    const float* bias;
    float* C;
    __nv_bfloat16* vt;
    float alpha;
    int relu;
    int M;
};
struct GemmArgs { GemmJob j[5]; };

template<int BM, int BN, int WM, int WN>
__global__ __launch_bounds__(256, 2) void gemm_tf32(GemmArgs args, int N, int K)
{
    constexpr int MT = WM / 16, NT = WN / 8;
    constexpr int SA = BM * 20, SB = BN * 20, STG = SA + SB;
    constexpr int AU = BM / 64;
    constexpr int BU = BN / 64;
    __shared__ uint32_t sm[2 * STG];

    const GemmJob jb = args.j[blockIdx.z];
    int M = jb.M;
    int bm = blockIdx.y * BM, bn = blockIdx.x * BN;
    if (bm >= M) return;
    int tid = threadIdx.x, warp = tid >> 5, lane = tid & 31;
    constexpr int WARPS_M = BM / WM;
    int wm = warp % WARPS_M, wn = warp / WARPS_M;
    int g = lane >> 2, tq = lane & 3;
    int R0 = wm * WM, N0 = wn * WN;

    float acc[MT][NT][4];
    #pragma unroll
    for (int mt = 0; mt < MT; mt++)
        #pragma unroll
        for (int nt = 0; nt < NT; nt++)
            #pragma unroll
            for (int i = 0; i < 4; i++) acc[mt][nt][i] = 0.f;

    int KT = K >> 4;
    uint32_t sbase = (uint32_t)__cvta_generic_to_shared(sm);

    uint32_t adst[AU], bdst[BU];
    const char* asrc[AU];
    const char* bsrc[BU];
    int asz[AU];
    #pragma unroll
    for (int i = 0; i < AU; i++) {
        int idx = tid + i * 256;
        int arow = idx >> 2, akq = (idx & 3) * 4;
        int row = bm + arow;
        int valid = row < M;
        asrc[i] = (const char*)(jb.A + (size_t)(valid ? row : 0) * K + akq);
        asz[i] = valid ? 16 : 0;
        adst[i] = sbase + (uint32_t)(arow * 20 + akq) * 4;
    }
    #pragma unroll
    for (int i = 0; i < BU; i++) {
        int idx = tid + i * 256;
        int brow = idx >> 2, bkq = (idx & 3) * 4;
        bsrc[i] = (const char*)(jb.B + (size_t)(bn + brow) * K + bkq);
        bdst[i] = sbase + (uint32_t)(SA + brow * 20 + bkq) * 4;
    }

    // prologue: stage 0
    #pragma unroll
    for (int i = 0; i < AU; i++) cpa16(adst[i], asrc[i], asz[i]);
    #pragma unroll
    for (int i = 0; i < BU; i++) cpa16(bdst[i], bsrc[i], 16);
    CP_COMMIT();
    CP_WAIT0();
    __syncthreads();

    for (int kt = 0; kt < KT; kt++) {
        int s = kt & 1;
        if (kt + 1 < KT) {
            int kb = (kt + 1) * 64;            // bytes along K
            uint32_t off = (uint32_t)((s ^ 1) * STG) * 4;
            #pragma unroll
            for (int i = 0; i < AU; i++) cpa16(adst[i] + off, asrc[i] + kb, asz[i]);
            #pragma unroll
            for (int i = 0; i < BU; i++) cpa16(bdst[i] + off, bsrc[i] + kb, 16);
            CP_COMMIT();
        }
        const uint32_t* sA = sm + s * STG;
        const uint32_t* sB = sA + SA;
        #pragma unroll
        for (int ks = 0; ks < 2; ks++) {
            int ko = ks * 8;
            uint32_t aF[MT][4], bF[NT][2];
            #pragma unroll
            for (int mt = 0; mt < MT; mt++) {
                int r = R0 + mt * 16 + g;
                aF[mt][0] = sA[r * 20 + ko + tq];
                aF[mt][1] = sA[(r + 8) * 20 + ko + tq];
                aF[mt][2] = sA[r * 20 + ko + tq + 4];
                aF[mt][3] = sA[(r + 8) * 20 + ko + tq + 4];
            }
            #pragma unroll
            for (int nt = 0; nt < NT; nt++) {
                int rn = N0 + nt * 8 + g;
                bF[nt][0] = sB[rn * 20 + ko + tq];
                bF[nt][1] = sB[rn * 20 + ko + tq + 4];
            }
            #pragma unroll
            for (int mt = 0; mt < MT; mt++)
                #pragma unroll
                for (int nt = 0; nt < NT; nt++)
                    mma_tf32(acc[mt][nt], aF[mt], bF[nt]);
        }
        if (kt + 1 < KT) {
            CP_WAIT0();
            __syncthreads();
        }
    }

    #pragma unroll
    for (int mt = 0; mt < MT; mt++)
        #pragma unroll
        for (int nt = 0; nt < NT; nt++) {
            int r = bm + R0 + mt * 16 + g;
            int cn = bn + N0 + nt * 8 + tq * 2;
            float b0 = jb.bias[cn], b1 = jb.bias[cn + 1];
            float o0 = (acc[mt][nt][0] + b0) * jb.alpha;
            float o1 = (acc[mt][nt][1] + b1) * jb.alpha;
            float o2 = (acc[mt][nt][2] + b0) * jb.alpha;
            float o3 = (acc[mt][nt][3] + b1) * jb.alpha;
            if (jb.relu) {
                o0 = fmaxf(o0, 0.f); o1 = fmaxf(o1, 0.f);
                o2 = fmaxf(o2, 0.f); o3 = fmaxf(o3, 0.f);
            }
            if (jb.vt) {
                int n0 = cn >> 5, d0 = cn & 31;
                if (r < M) {
                    int bb = r / NQ, q = r - bb * NQ;
                    size_t base = ((size_t)(bb * NH + n0) * HD) * NQ + q;
                    jb.vt[base + (size_t)d0 * NQ]       = __float2bfloat16(o0);
                    jb.vt[base + (size_t)(d0 + 1) * NQ] = __float2bfloat16(o1);
                }
                if (r + 8 < M) {
                    int bb = (r + 8) / NQ, q = (r + 8) - bb * NQ;
                    size_t base = ((size_t)(bb * NH + n0) * HD) * NQ + q;
                    jb.vt[base + (size_t)d0 * NQ]       = __float2bfloat16(o2);
                    jb.vt[base + (size_t)(d0 + 1) * NQ] = __float2bfloat16(o3);
                }
            } else {
                if (r < M)
                    *(float2*)(jb.C + (size_t)r * N + cn) = make_float2(o0, o1);
                if (r + 8 < M)
                    *(float2*)(jb.C + (size_t)(r + 8) * N + cn) = make_float2(o2, o3);
            }
        }
}

// ------------------------- fused attention (256 thr, parallel scores) -----------
#define AT_ARS  0
#define AT_ACS  2304
#define AT_QKR  (2304+3648)
#define AT_QKC  (AT_QKR + 4608)
#define AT_TOTAL_U32 (AT_QKC + 4608)

__global__ __launch_bounds__(256) void attn_fused(
    const float* __restrict__ qr, const float* __restrict__ qc,
    const float* __restrict__ kr, const float* __restrict__ kc,
    const unsigned char* __restrict__ mask,
    const __nv_bfloat16* __restrict__ vt, float* __restrict__ attn)
{
    extern __shared__ uint32_t dyn[];
    uint32_t* ARs = dyn + AT_ARS;
    float*    ACs = (float*)(dyn + AT_ACS);
    uint32_t* ub  = dyn + AT_QKR;          // combine-phase alias of QKr
    __shared__ unsigned char Ms[2][64];

    int b = blockIdx.z, n = blockIdx.y, q0 = blockIdx.x * 64;
    int tid = threadIdx.x, warp = tid >> 5, lane = tid & 31;
    int g = lane >> 2, tq = lane & 3;

    // zero ARs K-pad
    for (int i = tid; i < 64 * 4; i += 256) {
        int q = i >> 2;
        ARs[q * 36 + 28 + (i & 3)] = 0;
    }

    // ---- score phases IN PARALLEL: warps 0-3 row, warps 4-7 col ----
    {
        int which = warp >> 2;
        int wl = warp & 3;
        int ht = tid & 127;
        const float* q  = which ? qc : qr;
        const float* kk = which ? kc : kr;
        int mstride     = which ? LL : 1;
        uint32_t* Qs = dyn + (which ? AT_QKC : AT_QKR);
        uint32_t* Ks = Qs + 2304;

        {
            int rq = ht >> 1, hf = (ht & 1) * 16;
            const uint32_t* qp = (const uint32_t*)(q + ((size_t)(b * NQ + q0 + rq)) * CC + n * HD + hf);
            #pragma unroll
            for (int j = 0; j < 4; j++)
                *(uint4*)(Qs + rq * 36 + hf + j * 4) = *(const uint4*)(qp + j * 4);
        }
        for (int i = ht; i < LL * HD; i += 128) {
            int l = i >> 5, d = i & 31;
            Ks[d * 72 + l] = __float_as_uint(kk[((size_t)(b * LL + l)) * CC + n * HD + d]);
        }
        if (ht < LL) Ms[which][ht] = mask[b * NQ + ht * mstride];
        __syncthreads();

        int rb = wl * 16;
        uint32_t a[4][4];
        #pragma unroll
        for (int ks = 0; ks < 4; ks++) {
            a[ks][0] = Qs[(rb + g) * 36 + ks * 8 + tq];
            a[ks][1] = Qs[(rb + g + 8) * 36 + ks * 8 + tq];
            a[ks][2] = Qs[(rb + g) * 36 + ks * 8 + tq + 4];
            a[ks][3] = Qs[(rb + g + 8) * 36 + ks * 8 + tq + 4];
        }
        float c[7][4];
        #pragma unroll
        for (int nt = 0; nt < 7; nt++)
            #pragma unroll
            for (int i = 0; i < 4; i++) c[nt][i] = 0.f;
        #pragma unroll
        for (int nt = 0; nt < 7; nt++)
            #pragma unroll
            for (int ks = 0; ks < 4; ks++) {
                uint32_t bf[2] = { Ks[(ks * 8 + tq) * 72 + nt * 8 + g],
                                   Ks[(ks * 8 + tq + 4) * 72 + nt * 8 + g] };
                mma_tf32(c[nt], a[ks], bf);
            }

        float m0 = -3.0e38f, m1 = -3.0e38f;
        #pragma unroll
        for (int nt = 0; nt < 7; nt++) {
            int col = nt * 8 + tq * 2;
            if (Ms[which][col])     { c[nt][0] = NEGF; c[nt][2] = NEGF; }
            if (Ms[which][col + 1]) { c[nt][1] = NEGF; c[nt][3] = NEGF; }
            m0 = fmaxf(m0, fmaxf(c[nt][0], c[nt][1]));
            m1 = fmaxf(m1, fmaxf(c[nt][2], c[nt][3]));
        }
        #pragma unroll
        for (int o = 1; o <= 2; o <<= 1) {
            m0 = fmaxf(m0, __shfl_xor_sync(0xffffffffu, m0, o));
            m1 = fmaxf(m1, __shfl_xor_sync(0xffffffffu, m1, o));
        }
        float s0 = 0.f, s1 = 0.f;
        #pragma unroll
        for (int nt = 0; nt < 7; nt++) {
            c[nt][0] = __expf(c[nt][0] - m0);
            c[nt][1] = __expf(c[nt][1] - m0);
            c[nt][2] = __expf(c[nt][2] - m1);
            c[nt][3] = __expf(c[nt][3] - m1);
            s0 += c[nt][0] + c[nt][1];
            s1 += c[nt][2] + c[nt][3];
        }
        #pragma unroll
        for (int o = 1; o <= 2; o <<= 1) {
            s0 += __shfl_xor_sync(0xffffffffu, s0, o);
            s1 += __shfl_xor_sync(0xffffffffu, s1, o);
        }
        float i0 = 1.0f / s0, i1 = 1.0f / s1;
        if (which == 0) {
            #pragma unroll
            for (int nt = 0; nt < 7; nt++) {
                ARs[(rb + g) * 36 + nt * 4 + tq]     = pack_bf16(c[nt][0] * i0, c[nt][1] * i0);
                ARs[(rb + g + 8) * 36 + nt * 4 + tq] = pack_bf16(c[nt][2] * i1, c[nt][3] * i1);
            }
        } else {
            #pragma unroll
            for (int nt = 0; nt < 7; nt++) {
                int col = nt * 8 + tq * 2;
                ACs[(rb + g) * 57 + col]         = c[nt][0] * i0;
                ACs[(rb + g) * 57 + col + 1]     = c[nt][1] * i0;
                ACs[(rb + g + 8) * 57 + col]     = c[nt][2] * i1;
                ACs[(rb + g + 8) * 57 + col + 1] = c[nt][3] * i1;
            }
        }
    }
    __syncthreads();   // scores done; QKr region (ub) free for V staging

    // ---- combine: bf16 m16n8k16, 8 warps tiled 2(q) x 4(d) ----
    int wq = warp & 1, wd = warp >> 1;
    int QB = wq * 32, DB = wd * 8;

    uint32_t af[4][2][4];
    #pragma unroll
    for (int ks = 0; ks < 4; ks++)
        #pragma unroll
        for (int mt = 0; mt < 2; mt++) {
            int r = QB + mt * 16 + g;
            af[ks][mt][0] = ARs[r * 36 + ks * 8 + tq];
            af[ks][mt][1] = ARs[(r + 8) * 36 + ks * 8 + tq];
            af[ks][mt][2] = ARs[r * 36 + ks * 8 + tq + 4];
            af[ks][mt][3] = ARs[(r + 8) * 36 + ks * 8 + tq + 4];
        }

    // V staging via cp.async: 224 uint4/slab, threads 0..223 one each
    const __nv_bfloat16* vtb = vt + ((size_t)(b * NH + n) * HD) * NQ;
    int sact = tid < 224;
    int sd_ = tid / 7, sc4 = tid % 7;
    uint32_t ubase = (uint32_t)__cvta_generic_to_shared(ub);
    uint32_t vdst = ubase + (uint32_t)(sd_ * 36 + sc4 * 4) * 4;
    const char* vsrc = (const char*)vtb + ((size_t)sd_ * 392 + sc4) * 16;
    // zero V-stage pads: 2 stages x 32 d x 4 = 256, one per thread
    {
        int i = tid;
        ub[(i >> 7) * 1152 + ((i >> 2) & 31) * 36 + 28 + (i & 3)] = 0;
    }
    if (sact) cpa16(vdst, vsrc, 16);       // h = 0 into stage 0
    CP_COMMIT();
    CP_WAIT0();
    __syncthreads();

    float oacc[2][4];
    #pragma unroll
    for (int mt = 0; mt < 2; mt++)
        #pragma unroll
        for (int i = 0; i < 4; i++) oacc[mt][i] = 0.f;

    for (int h = 0; h < LL; h++) {
        int s = h & 1;
        if (h + 1 < LL) {
            if (sact)
                cpa16(vdst + (uint32_t)((s ^ 1) * 1152) * 4,
                      vsrc + (size_t)(h + 1) * LL * 2, 16);
            CP_COMMIT();
        }
        float p[2][4];
        #pragma unroll
        for (int mt = 0; mt < 2; mt++)
            #pragma unroll
            for (int i = 0; i < 4; i++) p[mt][i] = 0.f;

        const uint32_t* row = ub + s * 1152 + (DB + g) * 36;
        #pragma unroll
        for (int ks = 0; ks < 4; ks++) {
            uint32_t bf[2] = { row[ks * 8 + tq], row[ks * 8 + tq + 4] };
            #pragma unroll
            for (int mt = 0; mt < 2; mt++)
                mma_bf16(p[mt], af[ks][mt], bf);
        }

        #pragma unroll
        for (int mt = 0; mt < 2; mt++) {
            float ac0 = ACs[(QB + mt * 16 + g) * 57 + h];
            float ac1 = ACs[(QB + mt * 16 + g + 8) * 57 + h];
            oacc[mt][0] += ac0 * p[mt][0];
            oacc[mt][1] += ac0 * p[mt][1];
            oacc[mt][2] += ac1 * p[mt][2];
            oacc[mt][3] += ac1 * p[mt][3];
        }
        if (h + 1 < LL) {
            CP_WAIT0();
            __syncthreads();
        }
    }

    #pragma unroll
    for (int mt = 0; mt < 2; mt++) {
        int r = q0 + QB + mt * 16 + g;
        int col = n * HD + DB + tq * 2;
        *(float2*)(attn + ((size_t)(b * NQ) + r) * CC + col)
            = make_float2(oacc[mt][0], oacc[mt][1]);
        *(float2*)(attn + ((size_t)(b * NQ) + r + 8) * CC + col)
            = make_float2(oacc[mt][2], oacc[mt][3]);
    }
}

// ------------------------- residual + layernorm --------------------------------
__global__ __launch_bounds__(256) void add_ln(
    const float* __restrict__ A, const float* __restrict__ B,
    const float* __restrict__ gg, const float* __restrict__ be,
    float* __restrict__ out, int transpose_out)
{
    __shared__ float tile[256 * 33];
    int row0 = blockIdx.x * 32;
    int b = row0 / NQ;
    int qg0 = row0 % NQ;
    int tid = threadIdx.x, warp = tid >> 5, lane = tid & 31;

    float4 g0 = *(const float4*)(gg + lane * 4);
    float4 g1 = *(const float4*)(gg + 128 + lane * 4);
    float4 e0 = *(const float4*)(be + lane * 4);
    float4 e1 = *(const float4*)(be + 128 + lane * 4);

    #pragma unroll
    for (int rr = 0; rr < 4; rr++) {
        int rloc = warp * 4 + rr;
        size_t base = (size_t)(row0 + rloc) * CC;
        float4 a0 = *(const float4*)(A + base + lane * 4);
        float4 b0 = *(const float4*)(B + base + lane * 4);
        float4 a1 = *(const float4*)(A + base + 128 + lane * 4);
        float4 b1 = *(const float4*)(B + base + 128 + lane * 4);
        float v0x = a0.x + b0.x, v0y = a0.y + b0.y, v0z = a0.z + b0.z, v0w = a0.w + b0.w;
        float v1x = a1.x + b1.x, v1y = a1.y + b1.y, v1z = a1.z + b1.z, v1w = a1.w + b1.w;
        float s  = v0x + v0y + v0z + v0w + v1x + v1y + v1z + v1w;
        float s2 = v0x*v0x + v0y*v0y + v0z*v0z + v0w*v0w
                 + v1x*v1x + v1y*v1y + v1z*v1z + v1w*v1w;
        #pragma unroll
        for (int o = 16; o; o >>= 1) {
            s  += __shfl_xor_sync(0xffffffffu, s,  o);
            s2 += __shfl_xor_sync(0xffffffffu, s2, o);
        }
        float mean = s * (1.0f / CC);
        float var = s2 * (1.0f / CC) - mean * mean;
        float rstd = rsqrtf(var + 1e-5f);
        float r0x = (v0x - mean) * rstd * g0.x + e0.x;
        float r0y = (v0y - mean) * rstd * g0.y + e0.y;
        float r0z = (v0z - mean) * rstd * g0.z + e0.z;
        float r0w = (v0w - mean) * rstd * g0.w + e0.w;
        float r1x = (v1x - mean) * rstd * g1.x + e1.x;
        float r1y = (v1y - mean) * rstd * g1.y + e1.y;
        float r1z = (v1z - mean) * rstd * g1.z + e1.z;
        float r1w = (v1w - mean) * rstd * g1.w + e1.w;
        if (!transpose_out) {
            *(float4*)(out + base + lane * 4) = make_float4(r0x, r0y, r0z, r0w);
            *(float4*)(out + base + 128 + lane * 4) = make_float4(r1x, r1y, r1z, r1w);
        } else {
            int c = lane * 4;
            tile[(c + 0) * 33 + rloc] = r0x;
            tile[(c + 1) * 33 + rloc] = r0y;
            tile[(c + 2) * 33 + rloc] = r0z;
            tile[(c + 3) * 33 + rloc] = r0w;
            tile[(c + 128) * 33 + rloc] = r1x;
            tile[(c + 129) * 33 + rloc] = r1y;
            tile[(c + 130) * 33 + rloc] = r1z;
            tile[(c + 131) * 33 + rloc] = r1w;
        }
    }
    if (transpose_out) {
        __syncthreads();
        int qv = tid & 31;
        int cb = tid >> 5;
        #pragma unroll 8
        for (int k = 0; k < 32; k++) {
            int c = cb + k * 8;
            out[((size_t)(b * CC + c)) * NQ + qg0 + qv] = tile[c * 33 + qv];
        }
    }
}

// ------------------------- launch ----------------------------------------------
extern "C" void kernel_launch(void* const* d_in, const int* in_sizes, int n_in,
                              void* d_out, int out_size)
{
    const float* src   = (const float*)d_in[0];
    const unsigned char* pm = (const unsigned char*)d_in[1];
    const float* pr    = (const float*)d_in[2];
    const float* pc    = (const float*)d_in[3];
    const float* w_q_row = (const float*)d_in[4];
    const float* b_q_row = (const float*)d_in[5];
    const float* w_q_col = (const float*)d_in[6];
    const float* b_q_col = (const float*)d_in[7];
    const float* w_k_row = (const float*)d_in[8];
    const float* b_k_row = (const float*)d_in[9];
    const float* w_k_col = (const float*)d_in[10];
    const float* b_k_col = (const float*)d_in[11];
    const float* w_v   = (const float*)d_in[12];
    const float* b_v   = (const float*)d_in[13];
    const float* w_out = (const float*)d_in[14];
    const float* b_out = (const float*)d_in[15];
    const float* n1g   = (const float*)d_in[16];
    const float* n1b   = (const float*)d_in[17];
    const float* l1w   = (const float*)d_in[18];
    const float* l1b   = (const float*)d_in[19];
    const float* l2w   = (const float*)d_in[20];
    const float* l2b   = (const float*)d_in[21];
    const float* n2g   = (const float*)d_in[22];
    const float* n2b   = (const float*)d_in[23];
    float* out = (float*)d_out;

    float* F = nullptr;
    __nv_bfloat16* VT = nullptr;
    cudaGetSymbolAddress((void**)&F, g_f);
    cudaGetSymbolAddress((void**)&VT, g_vt);
    cudaFuncSetAttribute(attn_fused, cudaFuncAttributeMaxDynamicSharedMemorySize,
                         AT_TOTAL_U32 * 4);

    prep_kernel<<<dim3(NQ / 64, CC / 64, BZV), 256>>>(
        src, pr, pc, F + F_X, F + F_XPR, F + F_XPC);

    pool_kernel<<<BZV * LL * CC / 256, 256>>>(
        F + F_X, pr, pc, F + F_PR, F + F_PC);

    {
        GemmArgs a;
        a.j[0] = {F+F_XPR, w_q_row, b_q_row, F+F_QROW, nullptr, SCALE, 0, MQ};
        a.j[1] = {F+F_XPC, w_q_col, b_q_col, F+F_QCOL, nullptr, SCALE, 0, MQ};
        a.j[2] = {F+F_X,   w_v,     b_v,     nullptr,  VT,      1.0f, 0, MQ};
        a.j[3] = {F+F_PR,  w_k_row, b_k_row, F+F_KROW, nullptr, 1.0f, 0, BZV*LL};
        a.j[4] = {F+F_PC,  w_k_col, b_k_col, F+F_KCOL, nullptr, 1.0f, 0, BZV*LL};
        gemm_tf32<128,128,64,32><<<dim3(CC/128, MQ/128, 5), 256>>>(a, CC, CC);
    }

    attn_fused<<<dim3(NQ/64, NH, BZV), 256, AT_TOTAL_U32 * 4>>>(
        F+F_QROW, F+F_QCOL, F+F_KROW, F+F_KCOL, pm, VT, F+F_ATTN);

    {
        GemmArgs a;
        a.j[0] = {F+F_ATTN, w_out, b_out, F+F_ATTNOUT, nullptr, 1.0f, 0, MQ};
        a.j[1] = a.j[0]; a.j[2] = a.j[0]; a.j[3] = a.j[0]; a.j[4] = a.j[0];
        gemm_tf32<128,128,64,32><<<dim3(CC/128, MQ/128, 1), 256>>>(a, CC, CC);
    }
    add_ln<<<MQ/32, 256>>>(F+F_X, F+F_ATTNOUT, n1g, n1b, F+F_X1, 0);

    {
        GemmArgs a;
        a.j[0] = {F+F_X1, l1w, l1b, F+F_FFN, nullptr, 1.0f, 1, MQ};
        a.j[1] = a.j[0]; a.j[2] = a.j[0]; a.j[3] = a.j[0]; a.j[4] = a.j[0];
        gemm_tf32<128,128,64,32><<<dim3(DFFN/128, MQ/128, 1), 256>>>(a, DFFN, CC);
    }
    {
        GemmArgs a;
        a.j[0] = {F+F_FFN, l2w, l2b, F+F_Y, nullptr, 1.0f, 0, MQ};
        a.j[1] = a.j[0]; a.j[2] = a.j[0]; a.j[3] = a.j[0]; a.j[4] = a.j[0];
        gemm_tf32<128,128,64,32><<<dim3(CC/128, MQ/128, 1), 256>>>(a, CC, DFFN);
    }
    add_ln<<<MQ/32, 256>>>(F+F_X1, F+F_Y, n2g, n2b, out, 1);
}